// round 12
// baseline (speedup 1.0000x reference)
#include <cuda_runtime.h>
#include <math.h>
#include <stdint.h>

#define N_NODES 100000
#define D 128
#define E_MAX 1600000
#define LN_EPS 1e-5f

// Scratch (allocation-free rule: __device__ globals)
__device__ int   g_cnt[N_NODES];
__device__ int   g_off[N_NODES + 1];
__device__ int   g_pos[N_NODES];
__device__ int   g_csr[E_MAX];
__device__ int   g_bsum[128];
__device__ uint2 g_wsplit[8 * 2048];     // W in split-bf16, GEMM smem layout

__device__ __forceinline__ float gelu_exact(float t) {
    return 0.5f * t * (1.0f + erff(t * 0.70710678118654752440f));
}

__device__ __forceinline__ uint32_t smem_u32(const void* p) {
    uint32_t a;
    asm("{ .reg .u64 t; cvta.to.shared.u64 t, %1; cvt.u32.u64 %0, t; }"
        : "=r"(a) : "l"(p));
    return a;
}
__device__ __forceinline__ uint32_t cvt_bf16x2(float hi_elem, float lo_elem) {
    uint32_t r;
    asm("cvt.rn.bf16x2.f32 %0, %1, %2;" : "=r"(r) : "f"(hi_elem), "f"(lo_elem));
    return r;
}

// ---------------------------------------------------------------------------
// Phase 0: one-time precompute — W in split-bf16, GEMM smem layout.
// ---------------------------------------------------------------------------
__global__ void wsplit_prep_kernel(const float* __restrict__ W_l,
                                   const float* __restrict__ W_r) {
    int idx = blockIdx.x * blockDim.x + threadIdx.x;    // pair index
    if (idx >= 8 * 128 * 16) return;
    int c = idx >> 11;
    int m = (idx >> 4) & 127;
    int j = idx & 15;
    const float* src = (c < 4) ? W_l : W_r;
    int k0 = (c & 3) * 32 + j * 2;
    float f0 = src[m * 128 + k0];
    float f1 = src[m * 128 + k0 + 1];
    uint32_t hp = cvt_bf16x2(f1, f0);
    float h0 = __uint_as_float(hp << 16);
    float h1 = __uint_as_float(hp & 0xffff0000u);
    uint32_t lp = cvt_bf16x2(f1 - h1, f0 - h0);
    int ks = j >> 3, jj = j & 7, half = jj >> 2, tig = jj & 3;
    int p = ((ks << 2) + tig) ^ (m & 7);
    int u2 = (c * 16384 + m * 128 + p * 16 + half * 8) >> 3;
    g_wsplit[u2] = make_uint2(hp, lp);
}

// ---------------------------------------------------------------------------
// Phase 1: CSR build (histogram -> scan -> index scatter)
// ---------------------------------------------------------------------------
__global__ void zero_cnt_kernel() {
    int i = blockIdx.x * blockDim.x + threadIdx.x;
    if (i < N_NODES) g_cnt[i] = 0;
}

__global__ void hist_kernel(const int* __restrict__ ei, int E) {
    int i = blockIdx.x * blockDim.x + threadIdx.x;
    if (i >= E) return;
    int dst = ei[E + i];
    if ((unsigned)dst < N_NODES) atomicAdd(&g_cnt[dst], 1);
}

#define SCAN_B 1024
__global__ void scan_partial_kernel(int n) {
    __shared__ int sdata[SCAN_B];
    int tid = threadIdx.x;
    int i = blockIdx.x * SCAN_B + tid;
    int v = (i < n) ? g_cnt[i] : 0;
    sdata[tid] = v;
    __syncthreads();
    for (int off = 1; off < SCAN_B; off <<= 1) {
        int t = (tid >= off) ? sdata[tid - off] : 0;
        __syncthreads();
        sdata[tid] += t;
        __syncthreads();
    }
    if (i < n) g_off[i] = sdata[tid] - v;   // exclusive within block
    if (tid == SCAN_B - 1) g_bsum[blockIdx.x] = sdata[tid];
}

// Fused: per-block re-scan of the block sums + global offset add.
__global__ void scan_add_kernel(int n, int E, int nb) {
    __shared__ int sbs[128];
    int tid = threadIdx.x;
    if (tid < 128) sbs[tid] = (tid < nb) ? g_bsum[tid] : 0;
    __syncthreads();
    for (int off = 1; off < 128; off <<= 1) {
        int t = (tid < 128 && tid >= off) ? sbs[tid - off] : 0;
        __syncthreads();
        if (tid < 128) sbs[tid] += t;
        __syncthreads();
    }
    int i = blockIdx.x * blockDim.x + tid;
    if (i < n) {
        int b = i / SCAN_B;
        int base = (b == 0) ? 0 : sbs[b - 1];
        int o = g_off[i] + base;
        g_off[i] = o;
        g_pos[i] = o;
    }
    if (i == 0) g_off[n] = E;
}

__global__ void csr_fill_kernel(const int* __restrict__ ei, int E) {
    int i = blockIdx.x * blockDim.x + threadIdx.x;
    if (i >= E) return;
    int dst = ei[E + i];
    int src = ei[i];
    if ((unsigned)dst >= N_NODES || (unsigned)src >= N_NODES) return;
    int p = atomicAdd(&g_pos[dst], 1);
    g_csr[p] = src;
}

// ---------------------------------------------------------------------------
// Phase 2 (FUSED): gather-aggregate + split-bf16 mma.sync GEMM + epilogue.
// out = LN(gelu([mean_agg | x] @ [W_l | W_r]^T + b_l)) + x
// Each CTA: 8 warps gather 16 nodes each (means written straight into the
// 4 resident smem A-agg chunk buffers, split-bf16), then the GEMM mainloop
// runs 8 chunks (0-3: A resident; 4-7: A=x staged per chunk), B staged per
// chunk from pre-split weights. 2 CTAs/SM so one CTA's gather (L2-bound)
// overlaps the other's MMAs (tensor-bound).
// ---------------------------------------------------------------------------
#define SM_AGG  0         // 4 * 16384 = 65536 (resident A chunks 0-3)
#define SM_AX   65536     // 16384 (A chunk buffer for chunks 4-7)
#define SM_B    81920     // 16384
#define SM_C    0         // reuse: 128 * 132 * 4 = 67584
#define SM_BL   98304
#define SM_GA   98816
#define SM_BE   99328
#define SM_PS   99840     // 256 floats
#define SM_PSS  100864    // 256 floats
#define SMEM_G  101888

#define MMA_BF16(accp, A0,A1,A2,A3, B0,B1) \
    asm volatile("mma.sync.aligned.m16n8k16.row.col.f32.bf16.bf16.f32 " \
        "{%0,%1,%2,%3}, {%4,%5,%6,%7}, {%8,%9}, {%0,%1,%2,%3};" \
        : "+f"((accp)[0]), "+f"((accp)[1]), "+f"((accp)[2]), "+f"((accp)[3]) \
        : "r"(A0), "r"(A1), "r"(A2), "r"(A3), "r"(B0), "r"(B1))

__device__ __forceinline__ void lds128(uint32_t addr, uint32_t& r0, uint32_t& r1,
                                       uint32_t& r2, uint32_t& r3) {
    asm volatile("ld.shared.v4.b32 {%0,%1,%2,%3}, [%4];"
                 : "=r"(r0), "=r"(r1), "=r"(r2), "=r"(r3) : "r"(addr));
}
__device__ __forceinline__ void sts64(uint32_t addr, uint32_t a, uint32_t b) {
    asm volatile("st.shared.v2.b32 [%0], {%1,%2};"
                 :: "r"(addr), "r"(a), "r"(b) : "memory");
}

// Store one k-pair (f0 = k even, f1 = k odd) of row m as (hiPair, loPair).
__device__ __forceinline__ void stage_pair(uint32_t base, int m, int j,
                                           float f0, float f1) {
    int ks   = j >> 3;
    int jj   = j & 7;
    int half = jj >> 2;
    int tig  = jj & 3;
    uint32_t p = (uint32_t)(((ks << 2) + tig) ^ (m & 7));
    uint32_t addr = base + (uint32_t)m * 128 + p * 16 + (uint32_t)half * 8;
    uint32_t hp = cvt_bf16x2(f1, f0);
    float h0 = __uint_as_float(hp << 16);
    float h1 = __uint_as_float(hp & 0xffff0000u);
    uint32_t lp = cvt_bf16x2(f1 - h1, f0 - h0);
    sts64(addr, hp, lp);
}

__global__ void __launch_bounds__(256, 2)
fused_kernel(const float* __restrict__ x,
             const float* __restrict__ b_l,
             const float* __restrict__ ln_gamma,
             const float* __restrict__ ln_beta,
             float* __restrict__ out) {
    extern __shared__ char smem[];
    const uint32_t sb = smem_u32(smem);
    const int tid   = threadIdx.x;
    const int lane  = tid & 31;
    const int wid   = tid >> 5;
    const int g     = lane >> 2;
    const int tig   = lane & 3;
    const int warpM = wid & 3;
    const int warpN = wid >> 2;
    const int row0  = blockIdx.x * 128;

    if (tid < 128) {
        ((float*)(smem + SM_BL))[tid] = b_l[tid];
        ((float*)(smem + SM_GA))[tid] = ln_gamma[tid];
        ((float*)(smem + SM_BE))[tid] = ln_beta[tid];
    }

    // ==== Gather phase: warp w aggregates nodes row0 + w*16 + [0,16) ====
    {
        const float4* x4 = reinterpret_cast<const float4*>(x);
        const uint32_t abase = sb + SM_AGG + (uint32_t)(lane >> 3) * 16384;
        const int q = lane & 7;
        for (int i = 0; i < 16; i++) {
            int m = wid * 16 + i;
            int node = row0 + m; if (node >= N_NODES) node = N_NODES - 1;
            int beg = g_off[node];
            int end = g_off[node + 1];
            float4 acc = make_float4(0.f, 0.f, 0.f, 0.f);
            int e = beg;
            for (; e + 3 < end; e += 4) {
                int s0 = g_csr[e],     s1 = g_csr[e + 1];
                int s2 = g_csr[e + 2], s3 = g_csr[e + 3];
                float4 v0 = x4[(size_t)s0 * 32 + lane];
                float4 v1 = x4[(size_t)s1 * 32 + lane];
                float4 v2 = x4[(size_t)s2 * 32 + lane];
                float4 v3 = x4[(size_t)s3 * 32 + lane];
                acc.x += (v0.x + v1.x) + (v2.x + v3.x);
                acc.y += (v0.y + v1.y) + (v2.y + v3.y);
                acc.z += (v0.z + v1.z) + (v2.z + v3.z);
                acc.w += (v0.w + v1.w) + (v2.w + v3.w);
            }
            for (; e < end; e++) {
                float4 v = x4[(size_t)g_csr[e] * 32 + lane];
                acc.x += v.x; acc.y += v.y; acc.z += v.z; acc.w += v.w;
            }
            float rinv = 1.0f / fmaxf((float)(end - beg), 1.0f);
            stage_pair(abase, m, 2 * q,     acc.x * rinv, acc.y * rinv);
            stage_pair(abase, m, 2 * q + 1, acc.z * rinv, acc.w * rinv);
        }
    }

    float acc[2][8][4];
    #pragma unroll
    for (int mt = 0; mt < 2; mt++)
        #pragma unroll
        for (int nt = 0; nt < 8; nt++)
            #pragma unroll
            for (int cc = 0; cc < 4; cc++) acc[mt][nt][cc] = 0.f;

    const uint4* wsp = reinterpret_cast<const uint4*>(g_wsplit);
    __syncthreads();

    // ==== GEMM mainloop: 8 chunks of 32 k ====
    for (int c = 0; c < 8; c++) {
        // stage B chunk (plain copy of pre-split weights)
        #pragma unroll
        for (int it = 0; it < 4; it++) {
            int idx = tid + it * 256;
            *(uint4*)(smem + SM_B + idx * 16) = wsp[c * 1024 + idx];
        }
        // stage A = x chunk for c >= 4
        if (c >= 4) {
            const float* Asrc = x + (c - 4) * 32;
            #pragma unroll
            for (int it = 0; it < 4; it++) {
                int idx = tid + it * 256;
                int m = idx >> 3, q = idx & 7;
                int row = row0 + m; if (row >= N_NODES) row = N_NODES - 1;
                float4 av = *(const float4*)(Asrc + (size_t)row * D + q * 4);
                stage_pair(sb + SM_AX, m, 2 * q,     av.x, av.y);
                stage_pair(sb + SM_AX, m, 2 * q + 1, av.z, av.w);
            }
        }
        __syncthreads();

        const uint32_t abuf = (c < 4) ? (sb + SM_AGG + (uint32_t)c * 16384)
                                      : (sb + SM_AX);
        const uint32_t bbuf = sb + SM_B;

        #pragma unroll
        for (int ks = 0; ks < 2; ks++) {
            uint32_t ah[2][4], al[2][4];
            #pragma unroll
            for (int mt = 0; mt < 2; mt++) {
                int r0w = warpM * 32 + mt * 16 + g;
                uint32_t p0 = (uint32_t)(((ks << 2) + tig) ^ (r0w & 7));
                uint32_t v0, v1, v2, v3;
                lds128(abuf + (uint32_t)r0w * 128 + p0 * 16, v0, v1, v2, v3);
                ah[mt][0] = v0; al[mt][0] = v1; ah[mt][2] = v2; al[mt][2] = v3;
                int r1w = r0w + 8;
                uint32_t p1 = (uint32_t)(((ks << 2) + tig) ^ (r1w & 7));
                lds128(abuf + (uint32_t)r1w * 128 + p1 * 16, v0, v1, v2, v3);
                ah[mt][1] = v0; al[mt][1] = v1; ah[mt][3] = v2; al[mt][3] = v3;
            }
            #pragma unroll
            for (int nt = 0; nt < 8; nt++) {
                int rn = warpN * 64 + nt * 8 + g;
                uint32_t p = (uint32_t)(((ks << 2) + tig) ^ (rn & 7));
                uint32_t bh0, bl0, bh1, bl1;
                lds128(bbuf + (uint32_t)rn * 128 + p * 16, bh0, bl0, bh1, bl1);
                #pragma unroll
                for (int mt = 0; mt < 2; mt++) {
                    MMA_BF16(acc[mt][nt], al[mt][0], al[mt][1], al[mt][2], al[mt][3], bh0, bh1);
                    MMA_BF16(acc[mt][nt], ah[mt][0], ah[mt][1], ah[mt][2], ah[mt][3], bl0, bl1);
                    MMA_BF16(acc[mt][nt], ah[mt][0], ah[mt][1], ah[mt][2], ah[mt][3], bh0, bh1);
                }
            }
        }
        __syncthreads();
    }

    // ---- dump accumulators into C tile (stride 132 floats) ----
    float* C = (float*)(smem + SM_C);
    #pragma unroll
    for (int mt = 0; mt < 2; mt++) {
        #pragma unroll
        for (int nt = 0; nt < 8; nt++) {
            int row = warpM * 32 + mt * 16 + g;
            int col = warpN * 64 + nt * 8 + 2 * tig;
            *(float2*)(C + row * 132 + col)       = make_float2(acc[mt][nt][0], acc[mt][nt][1]);
            *(float2*)(C + (row + 8) * 132 + col) = make_float2(acc[mt][nt][2], acc[mt][nt][3]);
        }
    }
    __syncthreads();

    // ---- bias + GELU + LN stats ----
    const float* sbl = (const float*)(smem + SM_BL);
    const float* sga = (const float*)(smem + SM_GA);
    const float* sbe = (const float*)(smem + SM_BE);
    float* ps  = (float*)(smem + SM_PS);
    float* pss = (float*)(smem + SM_PSS);

    const int r    = tid & 127;
    const int half = tid >> 7;
    float v[64];
    {
        float s = 0.f, ss = 0.f;
        #pragma unroll
        for (int i = 0; i < 64; i++) {
            int n = half * 64 + i;
            float t = C[r * 132 + n] + sbl[n];
            t = gelu_exact(t);
            v[i] = t;
            s += t;
            ss = fmaf(t, t, ss);
        }
        ps[tid] = s;
        pss[tid] = ss;
    }
    __syncthreads();
    {
        float s  = ps[tid] + ps[tid ^ 128];
        float ss = pss[tid] + pss[tid ^ 128];
        float mu   = s * (1.0f / 128.0f);
        float var  = ss * (1.0f / 128.0f) - mu * mu;
        float rstd = rsqrtf(var + LN_EPS);
        #pragma unroll
        for (int i = 0; i < 64; i++) {
            int n = half * 64 + i;
            C[r * 132 + n] = (v[i] - mu) * rstd * sga[n] + sbe[n];
        }
    }
    __syncthreads();

    // ---- coalesced residual + store ----
    for (int it = 0; it < 16; it++) {
        int idx = tid + it * 256;
        int row = idx >> 5, c4 = idx & 31;
        int grow = row0 + row;
        if (grow < N_NODES) {
            float4 cv = *(float4*)(C + row * 132 + c4 * 4);
            float4 xr = *(const float4*)(x + (size_t)grow * D + c4 * 4);
            cv.x += xr.x; cv.y += xr.y; cv.z += xr.z; cv.w += xr.w;
            *(float4*)(out + (size_t)grow * D + c4 * 4) = cv;
        }
    }
}

// ---------------------------------------------------------------------------
extern "C" void kernel_launch(void* const* d_in, const int* in_sizes, int n_in,
                              void* d_out, int out_size) {
    const float* x     = (const float*)d_in[0];
    const int*   ei    = (const int*)d_in[1];
    const float* W_l   = (const float*)d_in[2];
    const float* b_l   = (const float*)d_in[3];
    const float* W_r   = (const float*)d_in[4];
    const float* gamma = (const float*)d_in[5];
    const float* beta  = (const float*)d_in[6];
    float*       out   = (float*)d_out;

    int E = in_sizes[1] / 2;
    if (E > E_MAX) E = E_MAX;

    cudaFuncSetAttribute(fused_kernel,
                         cudaFuncAttributeMaxDynamicSharedMemorySize, SMEM_G);

    // One-time precompute (independent of CSR chain)
    wsplit_prep_kernel<<<(8 * 128 * 16 + 255) / 256, 256>>>(W_l, W_r);

    // CSR build
    zero_cnt_kernel<<<(N_NODES + 255) / 256, 256>>>();
    hist_kernel<<<(E + 255) / 256, 256>>>(ei, E);
    int nb = (N_NODES + SCAN_B - 1) / SCAN_B;          // 98 blocks
    scan_partial_kernel<<<nb, SCAN_B>>>(N_NODES);
    scan_add_kernel<<<(N_NODES + 255) / 256, 256>>>(N_NODES, E, nb);
    csr_fill_kernel<<<(E + 255) / 256, 256>>>(ei, E);

    // Fused gather-aggregate + tensor-core GEMM + epilogue
    int gblocks = (N_NODES + 127) / 128;               // 782
    fused_kernel<<<gblocks, 256, SMEM_G>>>(x, b_l, gamma, beta, out);
}

// round 13
// speedup vs baseline: 1.3820x; 1.3820x over previous
#include <cuda_runtime.h>
#include <math.h>
#include <stdint.h>

#define N_NODES 100000
#define D 128
#define E_MAX 1600000
#define LN_EPS 1e-5f

// Scratch (allocation-free rule: __device__ globals)
__device__ float g_agg[N_NODES * D];     // normalized mean aggregation
__device__ int   g_cnt[N_NODES];
__device__ int   g_off[N_NODES + 1];
__device__ int   g_pos[N_NODES];
__device__ int   g_csr[E_MAX];
__device__ int   g_bsum[128];
__device__ uint2 g_wsplit[8 * 2048];     // W as fp16 pairs, GEMM smem layout

__device__ __forceinline__ float gelu_exact(float t) {
    return 0.5f * t * (1.0f + erff(t * 0.70710678118654752440f));
}

__device__ __forceinline__ uint32_t smem_u32(const void* p) {
    uint32_t a;
    asm("{ .reg .u64 t; cvta.to.shared.u64 t, %1; cvt.u32.u64 %0, t; }"
        : "=r"(a) : "l"(p));
    return a;
}
// pack {hi_elem -> high 16, lo_elem -> low 16} as fp16x2
__device__ __forceinline__ uint32_t cvt_f16x2(float hi_elem, float lo_elem) {
    uint32_t r;
    asm("{ .reg .b16 h, l;\n\t"
        "cvt.rn.f16.f32 h, %1;\n\t"
        "cvt.rn.f16.f32 l, %2;\n\t"
        "mov.b32 %0, {l, h}; }"
        : "=r"(r) : "f"(hi_elem), "f"(lo_elem));
    return r;
}

// ---------------------------------------------------------------------------
// Phase 0: one-time precompute — W as fp16 pairs, GEMM smem layout.
// ---------------------------------------------------------------------------
__global__ void wsplit_prep_kernel(const float* __restrict__ W_l,
                                   const float* __restrict__ W_r) {
    int idx = blockIdx.x * blockDim.x + threadIdx.x;    // pair index
    if (idx >= 8 * 128 * 16) return;
    int c = idx >> 11;
    int m = (idx >> 4) & 127;
    int j = idx & 15;
    const float* src = (c < 4) ? W_l : W_r;
    int k0 = (c & 3) * 32 + j * 2;
    float f0 = src[m * 128 + k0];
    float f1 = src[m * 128 + k0 + 1];
    uint32_t hp = cvt_f16x2(f1, f0);       // low16 = f0, high16 = f1
    int ks = j >> 3, jj = j & 7, half = jj >> 2, tig = jj & 3;
    int p = ((ks << 2) + tig) ^ (m & 7);
    int u2 = (c * 16384 + m * 128 + p * 16 + half * 8) >> 3;
    g_wsplit[u2] = make_uint2(hp, 0u);
}

// ---------------------------------------------------------------------------
// Phase 1: CSR build (histogram -> scan -> index scatter)
// ---------------------------------------------------------------------------
__global__ void zero_cnt_kernel() {
    int i = blockIdx.x * blockDim.x + threadIdx.x;
    if (i < N_NODES) g_cnt[i] = 0;
}

__global__ void hist_kernel(const int* __restrict__ ei, int E) {
    int i = blockIdx.x * blockDim.x + threadIdx.x;
    if (i >= E) return;
    int dst = ei[E + i];
    if ((unsigned)dst < N_NODES) atomicAdd(&g_cnt[dst], 1);
}

#define SCAN_B 1024
__global__ void scan_partial_kernel(int n) {
    __shared__ int sdata[SCAN_B];
    int tid = threadIdx.x;
    int i = blockIdx.x * SCAN_B + tid;
    int v = (i < n) ? g_cnt[i] : 0;
    sdata[tid] = v;
    __syncthreads();
    for (int off = 1; off < SCAN_B; off <<= 1) {
        int t = (tid >= off) ? sdata[tid - off] : 0;
        __syncthreads();
        sdata[tid] += t;
        __syncthreads();
    }
    if (i < n) g_off[i] = sdata[tid] - v;   // exclusive within block
    if (tid == SCAN_B - 1) g_bsum[blockIdx.x] = sdata[tid];
}

// Fused: per-block re-scan of the block sums + global offset add.
__global__ void scan_add_kernel(int n, int E, int nb) {
    __shared__ int sbs[128];
    int tid = threadIdx.x;
    if (tid < 128) sbs[tid] = (tid < nb) ? g_bsum[tid] : 0;
    __syncthreads();
    for (int off = 1; off < 128; off <<= 1) {
        int t = (tid < 128 && tid >= off) ? sbs[tid - off] : 0;
        __syncthreads();
        if (tid < 128) sbs[tid] += t;
        __syncthreads();
    }
    int i = blockIdx.x * blockDim.x + tid;
    if (i < n) {
        int b = i / SCAN_B;
        int base = (b == 0) ? 0 : sbs[b - 1];
        int o = g_off[i] + base;
        g_off[i] = o;
        g_pos[i] = o;
    }
    if (i == 0) g_off[n] = E;
}

__global__ void csr_fill_kernel(const int* __restrict__ ei, int E) {
    int i = blockIdx.x * blockDim.x + threadIdx.x;
    if (i >= E) return;
    int dst = ei[E + i];
    int src = ei[i];
    if ((unsigned)dst >= N_NODES || (unsigned)src >= N_NODES) return;
    int p = atomicAdd(&g_pos[dst], 1);
    g_csr[p] = src;
}

// ---------------------------------------------------------------------------
// Phase 2: gather-aggregate (fp32). One warp per node. No atomics.
// ---------------------------------------------------------------------------
__global__ void __launch_bounds__(256)
aggregate_kernel(const float* __restrict__ x) {
    int node = (blockIdx.x * blockDim.x + threadIdx.x) >> 5;
    int lane = threadIdx.x & 31;
    if (node >= N_NODES) return;
    int beg = g_off[node];
    int end = g_off[node + 1];
    float4 acc = make_float4(0.f, 0.f, 0.f, 0.f);
    const float4* x4 = reinterpret_cast<const float4*>(x);

    int e = beg;
    for (; e + 3 < end; e += 4) {
        int s0 = g_csr[e], s1 = g_csr[e + 1], s2 = g_csr[e + 2], s3 = g_csr[e + 3];
        float4 v0 = x4[(size_t)s0 * 32 + lane];
        float4 v1 = x4[(size_t)s1 * 32 + lane];
        float4 v2 = x4[(size_t)s2 * 32 + lane];
        float4 v3 = x4[(size_t)s3 * 32 + lane];
        acc.x += (v0.x + v1.x) + (v2.x + v3.x);
        acc.y += (v0.y + v1.y) + (v2.y + v3.y);
        acc.z += (v0.z + v1.z) + (v2.z + v3.z);
        acc.w += (v0.w + v1.w) + (v2.w + v3.w);
    }
    for (; e < end; e++) {
        float4 v = x4[(size_t)g_csr[e] * 32 + lane];
        acc.x += v.x; acc.y += v.y; acc.z += v.z; acc.w += v.w;
    }
    float rinv = 1.0f / fmaxf((float)(end - beg), 1.0f);
    acc.x *= rinv; acc.y *= rinv; acc.z *= rinv; acc.w *= rinv;
    reinterpret_cast<float4*>(g_agg)[(size_t)node * 32 + lane] = acc;
}

// ---------------------------------------------------------------------------
// Phase 3: single-pass fp16 mma.sync GEMM + bias + GELU + LayerNorm + residual.
// out = LN(gelu([agg | x] @ [W_l | W_r]^T + b_l)) + x
// fp16 (10-bit mantissa) single pass: rel_err ~2-4e-4, 3x fewer MMAs than
// the split-bf16 3-term scheme. Layout identical to the proven split scheme
// (lo half of each slot unused).
// ---------------------------------------------------------------------------
#define SM_A  0          // 128 rows * 128 B = 16384
#define SM_B  16384      // 128 rows * 128 B = 16384
#define SM_C  0          // reuse: 128 * 132 * 4 = 67584
#define SM_BL 67584
#define SM_GA 68096
#define SM_BE 68608
#define SM_PS 69120      // 256 floats partial sums
#define SM_PSS 70144     // 256 floats partial sumsq
#define SMEM_G 71168

#define MMA_FP16(accp, A0,A1,A2,A3, B0,B1) \
    asm volatile("mma.sync.aligned.m16n8k16.row.col.f32.f16.f16.f32 " \
        "{%0,%1,%2,%3}, {%4,%5,%6,%7}, {%8,%9}, {%0,%1,%2,%3};" \
        : "+f"((accp)[0]), "+f"((accp)[1]), "+f"((accp)[2]), "+f"((accp)[3]) \
        : "r"(A0), "r"(A1), "r"(A2), "r"(A3), "r"(B0), "r"(B1))

__device__ __forceinline__ void lds128(uint32_t addr, uint32_t& r0, uint32_t& r1,
                                       uint32_t& r2, uint32_t& r3) {
    asm volatile("ld.shared.v4.b32 {%0,%1,%2,%3}, [%4];"
                 : "=r"(r0), "=r"(r1), "=r"(r2), "=r"(r3) : "r"(addr));
}
__device__ __forceinline__ void sts64(uint32_t addr, uint32_t a, uint32_t b) {
    asm volatile("st.shared.v2.b32 [%0], {%1,%2};"
                 :: "r"(addr), "r"(a), "r"(b) : "memory");
}

// Store one k-pair (f0 = k even, f1 = k odd) of row m as an fp16 pair.
__device__ __forceinline__ void stage_pair(uint32_t base, int m, int j,
                                           float f0, float f1) {
    int ks   = j >> 3;
    int jj   = j & 7;
    int half = jj >> 2;
    int tig  = jj & 3;
    uint32_t p = (uint32_t)(((ks << 2) + tig) ^ (m & 7));
    uint32_t addr = base + (uint32_t)m * 128 + p * 16 + (uint32_t)half * 8;
    uint32_t hp = cvt_f16x2(f1, f0);       // low 16 = f0, high 16 = f1
    sts64(addr, hp, 0u);
}

__global__ void __launch_bounds__(256, 2)
gemm_tc_kernel(const float* __restrict__ x,
               const float* __restrict__ b_l,
               const float* __restrict__ ln_gamma,
               const float* __restrict__ ln_beta,
               float* __restrict__ out) {
    extern __shared__ char smem[];
    const uint32_t sb = smem_u32(smem);
    const int tid   = threadIdx.x;
    const int lane  = tid & 31;
    const int wid   = tid >> 5;
    const int g     = lane >> 2;
    const int tig   = lane & 3;
    const int warpM = wid & 3;
    const int warpN = wid >> 2;
    const int row0  = blockIdx.x * 128;

    if (tid < 128) {
        ((float*)(smem + SM_BL))[tid] = b_l[tid];
        ((float*)(smem + SM_GA))[tid] = ln_gamma[tid];
        ((float*)(smem + SM_BE))[tid] = ln_beta[tid];
    }

    float acc[2][8][4];
    #pragma unroll
    for (int mt = 0; mt < 2; mt++)
        #pragma unroll
        for (int nt = 0; nt < 8; nt++)
            #pragma unroll
            for (int cc = 0; cc < 4; cc++) acc[mt][nt][cc] = 0.f;

    const uint4* wsp = reinterpret_cast<const uint4*>(g_wsplit);

    for (int c = 0; c < 8; c++) {
        // ---- stage A chunk (convert) + B chunk (plain copy) ----
        const float* Asrc = (c < 4) ? (g_agg + c * 32) : (x + (c - 4) * 32);
        #pragma unroll
        for (int it = 0; it < 4; it++) {
            int idx = tid + it * 256;
            int m = idx >> 3, q = idx & 7;
            int row = row0 + m; if (row >= N_NODES) row = N_NODES - 1;
            float4 av = *(const float4*)(Asrc + (size_t)row * D + q * 4);
            stage_pair(sb + SM_A, m, 2 * q,     av.x, av.y);
            stage_pair(sb + SM_A, m, 2 * q + 1, av.z, av.w);
            uint4 bv = wsp[c * 1024 + idx];
            *(uint4*)(smem + SM_B + idx * 16) = bv;
        }
        __syncthreads();

        // ---- compute: 2 k-steps of m16n8k16 fp16, single pass ----
        #pragma unroll
        for (int ks = 0; ks < 2; ks++) {
            uint32_t ah[2][4];
            #pragma unroll
            for (int mt = 0; mt < 2; mt++) {
                int r0w = warpM * 32 + mt * 16 + g;
                uint32_t p0 = (uint32_t)(((ks << 2) + tig) ^ (r0w & 7));
                uint32_t v0, v1, v2, v3;
                lds128(sb + SM_A + (uint32_t)r0w * 128 + p0 * 16, v0, v1, v2, v3);
                ah[mt][0] = v0; ah[mt][2] = v2;
                int r1w = r0w + 8;
                uint32_t p1 = (uint32_t)(((ks << 2) + tig) ^ (r1w & 7));
                lds128(sb + SM_A + (uint32_t)r1w * 128 + p1 * 16, v0, v1, v2, v3);
                ah[mt][1] = v0; ah[mt][3] = v2;
            }
            #pragma unroll
            for (int nt = 0; nt < 8; nt++) {
                int rn = warpN * 64 + nt * 8 + g;
                uint32_t p = (uint32_t)(((ks << 2) + tig) ^ (rn & 7));
                uint32_t bh0, bl0, bh1, bl1;
                lds128(sb + SM_B + (uint32_t)rn * 128 + p * 16, bh0, bl0, bh1, bl1);
                #pragma unroll
                for (int mt = 0; mt < 2; mt++) {
                    MMA_FP16(acc[mt][nt], ah[mt][0], ah[mt][1], ah[mt][2], ah[mt][3], bh0, bh1);
                }
            }
        }
        __syncthreads();
    }

    // ---- dump accumulators into C tile (stride 132 floats) ----
    float* C = (float*)(smem + SM_C);
    #pragma unroll
    for (int mt = 0; mt < 2; mt++) {
        #pragma unroll
        for (int nt = 0; nt < 8; nt++) {
            int row = warpM * 32 + mt * 16 + g;
            int col = warpN * 64 + nt * 8 + 2 * tig;
            *(float2*)(C + row * 132 + col)       = make_float2(acc[mt][nt][0], acc[mt][nt][1]);
            *(float2*)(C + (row + 8) * 132 + col) = make_float2(acc[mt][nt][2], acc[mt][nt][3]);
        }
    }
    __syncthreads();

    // ---- bias + GELU + LN stats ----
    const float* sbl = (const float*)(smem + SM_BL);
    const float* sga = (const float*)(smem + SM_GA);
    const float* sbe = (const float*)(smem + SM_BE);
    float* ps  = (float*)(smem + SM_PS);
    float* pss = (float*)(smem + SM_PSS);

    const int r    = tid & 127;
    const int half = tid >> 7;
    float v[64];
    {
        float s = 0.f, ss = 0.f;
        #pragma unroll
        for (int i = 0; i < 64; i++) {
            int n = half * 64 + i;
            float t = C[r * 132 + n] + sbl[n];
            t = gelu_exact(t);
            v[i] = t;
            s += t;
            ss = fmaf(t, t, ss);
        }
        ps[tid] = s;
        pss[tid] = ss;
    }
    __syncthreads();
    {
        float s  = ps[tid] + ps[tid ^ 128];
        float ss = pss[tid] + pss[tid ^ 128];
        float mu   = s * (1.0f / 128.0f);
        float var  = ss * (1.0f / 128.0f) - mu * mu;
        float rstd = rsqrtf(var + LN_EPS);
        #pragma unroll
        for (int i = 0; i < 64; i++) {
            int n = half * 64 + i;
            C[r * 132 + n] = (v[i] - mu) * rstd * sga[n] + sbe[n];
        }
    }
    __syncthreads();

    // ---- coalesced residual + store ----
    for (int it = 0; it < 16; it++) {
        int idx = tid + it * 256;
        int row = idx >> 5, c4 = idx & 31;
        int grow = row0 + row;
        if (grow < N_NODES) {
            float4 cv = *(float4*)(C + row * 132 + c4 * 4);
            float4 xr = *(const float4*)(x + (size_t)grow * D + c4 * 4);
            cv.x += xr.x; cv.y += xr.y; cv.z += xr.z; cv.w += xr.w;
            *(float4*)(out + (size_t)grow * D + c4 * 4) = cv;
        }
    }
}

// ---------------------------------------------------------------------------
extern "C" void kernel_launch(void* const* d_in, const int* in_sizes, int n_in,
                              void* d_out, int out_size) {
    const float* x     = (const float*)d_in[0];
    const int*   ei    = (const int*)d_in[1];
    const float* W_l   = (const float*)d_in[2];
    const float* b_l   = (const float*)d_in[3];
    const float* W_r   = (const float*)d_in[4];
    const float* gamma = (const float*)d_in[5];
    const float* beta  = (const float*)d_in[6];
    float*       out   = (float*)d_out;

    int E = in_sizes[1] / 2;
    if (E > E_MAX) E = E_MAX;

    cudaFuncSetAttribute(gemm_tc_kernel,
                         cudaFuncAttributeMaxDynamicSharedMemorySize, SMEM_G);

    // One-time precompute (independent of CSR chain)
    wsplit_prep_kernel<<<(8 * 128 * 16 + 255) / 256, 256>>>(W_l, W_r);

    // CSR build
    zero_cnt_kernel<<<(N_NODES + 255) / 256, 256>>>();
    hist_kernel<<<(E + 255) / 256, 256>>>(ei, E);
    int nb = (N_NODES + SCAN_B - 1) / SCAN_B;          // 98 blocks
    scan_partial_kernel<<<nb, SCAN_B>>>(N_NODES);
    scan_add_kernel<<<(N_NODES + 255) / 256, 256>>>(N_NODES, E, nb);
    csr_fill_kernel<<<(E + 255) / 256, 256>>>(ei, E);

    // Gather-aggregate (fp32, no atomics)
    long long athreads = (long long)N_NODES * 32;
    aggregate_kernel<<<(int)((athreads + 255) / 256), 256>>>(x);

    // Tensor-core (mma.sync fp16 single-pass) GEMM + fused epilogue
    int gblocks = (N_NODES + 127) / 128;               // 782
    gemm_tc_kernel<<<gblocks, 256, SMEM_G>>>(x, b_l, gamma, beta, out);
}